// round 5
// baseline (speedup 1.0000x reference)
#include <cuda_runtime.h>
#include <math.h>

// Problem constants (B=1)
#define NH     16
#define NSEQ   8192
#define EDIM   64
#define CHUNKN 512
#define NCH    16
#define RT     64      // query rows per block
#define SCALE  0.125f  // 1/sqrt(64)
#define WCOLS  15872   // 512 + 15*1024

// smem leading dims (floats); all row bases 16B-aligned
#define QT_LD 72
#define KV_LD 260      // 256-col K pass + pad
#define VS_LD 68       // V row-major 64 + pad
#define S_LD  516

#define SM_QT 0
#define SM_KV (64 * QT_LD)                 // 4608
#define SM_S  (SM_KV + 64 * KV_LD)         // 21248
#define SMEM_FLOATS (SM_S + RT * S_LD)     // 54272 floats = 217088 B

// ---- packed f32x2 helpers ----
#define FMA2(d, a, b)  asm("fma.rn.f32x2 %0, %1, %2, %0;" : "+l"(d) : "l"(a), "l"(b))
#define MUL2(d, a, b)  asm("mul.rn.f32x2 %0, %1, %2;"     : "=l"(d) : "l"(a), "l"(b))
#define ADD2(d, a, b)  asm("add.rn.f32x2 %0, %1, %2;"     : "=l"(d) : "l"(a), "l"(b))
#define PACK2(p, x)    asm("mov.b64 %0, {%1, %1};"        : "=l"(p) : "r"(__float_as_uint(x)))

__global__ __launch_bounds__(256, 1)
void chunked_attn_kernel(const float* __restrict__ query,
                         const float* __restrict__ key,
                         const float* __restrict__ value,
                         float* __restrict__ out,
                         float* __restrict__ wts)
{
    extern __shared__ float sm[];
    float* Qt  = sm + SM_QT;   // Qt[e][i]  (e-major)
    float* KV  = sm + SM_KV;   // K pass tile KV[e][jj] (e-major) / V tile Vsm[jj][e] (row-major)
    float* S   = sm + SM_S;    // S[i][j]

    const int tid  = threadIdx.x;
    const int lane = tid & 31;
    const int wid  = tid >> 5;

    const int rt = blockIdx.x;           // row tile 0..7
    const int n  = blockIdx.y;           // chunk
    const int h  = blockIdx.z;           // head
    const int r0 = rt * RT;
    const int m  = (n == 0) ? 0 : n - 1; // effective key/value chunk

    const float* qbase = query + ((size_t)h * NSEQ + (size_t)n * CHUNKN + r0) * EDIM;
    const float* kbase = key   + ((size_t)h * NSEQ + (size_t)m * CHUNKN) * EDIM;
    const float* vbase = value + ((size_t)h * NSEQ + (size_t)m * CHUNKN) * EDIM;

    // ---- load Q tile transposed: Qt[e][i] ----
    for (int idx = tid; idx < RT * EDIM; idx += 256) {
        int i = idx >> 6, e = idx & 63;
        Qt[e * QT_LD + i] = qbase[(size_t)i * EDIM + e];
    }

    const int ktmax = (r0 + RT - 1) >> 7;    // highest live 128-key tile
    const int jend  = (ktmax + 1) * 128;
    const int npass = (ktmax + 2) >> 1;      // 256-col GEMM1 passes

    // ==================== GEMM1: S = scale * Q K^T, 64x256 passes ====================
    {
        const int txc = tid & 31;            // 32 col-groups
        const int tyr = tid >> 5;            // 8 row-groups
        unsigned long long sp; PACK2(sp, SCALE);

        for (int p = 0; p < npass; p++) {
            const int j0 = p * 256;
            __syncthreads();                 // protect KV (also orders Qt on p=0)
            for (int idx = tid; idx < 256 * 64; idx += 256) {
                int jj = idx >> 6, e = idx & 63;
                KV[e * KV_LD + jj] = kbase[(size_t)(j0 + jj) * EDIM + e];
            }
            __syncthreads();

            unsigned long long acc[8][4];
            #pragma unroll
            for (int r = 0; r < 8; r++)
                #pragma unroll
                for (int c = 0; c < 4; c++) acc[r][c] = 0ull;

            const float* qb = Qt + tyr * 8;
            const float* kb = KV + txc * 4;
            #pragma unroll 4
            for (int e = 0; e < EDIM; e++) {
                const float* qe = qb + e * QT_LD;
                float4 q0 = *(const float4*)qe;
                float4 q1 = *(const float4*)(qe + 4);
                const float* ke = kb + e * KV_LD;
                ulonglong2 k0 = *(const ulonglong2*)ke;          // cols txc*4..+3
                ulonglong2 k1 = *(const ulonglong2*)(ke + 128);  // cols 128+txc*4..+3
                float qs[8] = {q0.x, q0.y, q0.z, q0.w, q1.x, q1.y, q1.z, q1.w};
                #pragma unroll
                for (int r = 0; r < 8; r++) {
                    unsigned long long qq; PACK2(qq, qs[r]);
                    FMA2(acc[r][0], qq, k0.x);
                    FMA2(acc[r][1], qq, k0.y);
                    FMA2(acc[r][2], qq, k1.x);
                    FMA2(acc[r][3], qq, k1.y);
                }
            }

            #pragma unroll
            for (int r = 0; r < 8; r++) {
                float* srow = S + (tyr * 8 + r) * S_LD + j0 + txc * 4;
                unsigned long long m0, m1, m2, m3;
                MUL2(m0, acc[r][0], sp); MUL2(m1, acc[r][1], sp);
                MUL2(m2, acc[r][2], sp); MUL2(m3, acc[r][3], sp);
                ulonglong2 t0; t0.x = m0; t0.y = m1;
                ulonglong2 t1; t1.x = m2; t1.y = m3;
                *(ulonglong2*)srow         = t0;
                *(ulonglong2*)(srow + 128) = t1;
            }
        }
    }

    __syncthreads();

    // ==================== softmax + weights write (warp per row, 8 rows/warp) ====================
    const int wcolbase = (n == 0) ? 0 : 512 + (n - 1) * 1024;
    for (int i = wid * 8; i < wid * 8 + 8; i++) {
        const int rglob = r0 + i;
        float* srow = S + i * S_LD;

        float mx = -INFINITY;
        for (int j = lane; j <= rglob; j += 32) mx = fmaxf(mx, srow[j]);
        #pragma unroll
        for (int off = 16; off; off >>= 1) mx = fmaxf(mx, __shfl_xor_sync(0xffffffffu, mx, off));

        float sum = 0.f;
        for (int j = lane; j <= rglob; j += 32) {
            float ex = __expf(srow[j] - mx);
            srow[j] = ex;
            sum += ex;
        }
        #pragma unroll
        for (int off = 16; off; off >>= 1) sum += __shfl_xor_sync(0xffffffffu, sum, off);
        float inv = 1.f / sum;

        float* wrow = wts + ((size_t)h * CHUNKN + rglob) * WCOLS + wcolbase;
        for (int j = lane; j < jend; j += 32) {
            float a = (j <= rglob) ? srow[j] * inv : 0.f;
            srow[j] = a;            // zero masked region inside jend for GEMM2
            wrow[j] = a;
        }
        for (int j = jend + lane; j < CHUNKN; j += 32) wrow[j] = 0.f;
        if (n > 0)
            for (int j = CHUNKN + lane; j < 2 * CHUNKN; j += 32) wrow[j] = 0.f;
    }

    // ==================== GEMM2: O = A V, 8x8 tiles, 4-way j-subslice + shfl reduce ====================
    {
        const int sub   = tid & 3;           // j sub-slice (interleaved by 4)
        const int tilei = tid >> 2;          // 0..63 output tile
        const int ei4   = (tilei & 7) * 4;   // e col base (plus +32 half)
        const int ii    = (tilei >> 3) * 8;  // row base (= wid*8)
        float* Vsm = KV;                     // reuse: Vsm[jj][e], VS_LD

        unsigned long long c2[8][4];
        #pragma unroll
        for (int r = 0; r < 8; r++)
            #pragma unroll
            for (int c = 0; c < 4; c++) c2[r][c] = 0ull;

        for (int kt = 0; kt <= ktmax; kt++) {
            __syncthreads();                 // prior tile consumed / softmax done (kt=0)
            for (int idx = tid; idx < 128 * 16; idx += 256) {
                int jj = idx >> 4, e4 = (idx & 15) << 2;
                *(float4*)(Vsm + jj * VS_LD + e4) =
                    *(const float4*)(vbase + (size_t)(kt * 128 + jj) * EDIM + e4);
            }
            __syncthreads();

            const float* Ab  = S   + ii * S_LD + kt * 128 + sub * 4;
            const float* Vb0 = Vsm + (sub * 4) * VS_LD + ei4;

            #pragma unroll 2
            for (int mm = 0; mm < 8; mm++) {
                float4 ar[8];
                #pragma unroll
                for (int r = 0; r < 8; r++)
                    ar[r] = *(const float4*)(Ab + r * S_LD + mm * 16);
                #pragma unroll
                for (int jr = 0; jr < 4; jr++) {
                    const float* vp = Vb0 + (mm * 16 + jr) * VS_LD;
                    ulonglong2 vlo = *(const ulonglong2*)vp;          // cols ei4..+3
                    ulonglong2 vhi = *(const ulonglong2*)(vp + 32);   // cols 32+ei4..+3
                    #pragma unroll
                    for (int r = 0; r < 8; r++) {
                        float av = (jr == 0) ? ar[r].x : (jr == 1) ? ar[r].y
                                 : (jr == 2) ? ar[r].z : ar[r].w;
                        unsigned long long pa; PACK2(pa, av);
                        FMA2(c2[r][0], pa, vlo.x);
                        FMA2(c2[r][1], pa, vlo.y);
                        FMA2(c2[r][2], pa, vhi.x);
                        FMA2(c2[r][3], pa, vhi.y);
                    }
                }
            }
        }

        // butterfly-reduce the 4 j-subslices (lanes xor 1, xor 2 share a tile)
        #pragma unroll
        for (int r = 0; r < 8; r++)
            #pragma unroll
            for (int c = 0; c < 4; c++) {
                unsigned long long o;
                o = __shfl_xor_sync(0xffffffffu, c2[r][c], 1);
                ADD2(c2[r][c], c2[r][c], o);
                o = __shfl_xor_sync(0xffffffffu, c2[r][c], 2);
                ADD2(c2[r][c], c2[r][c], o);
            }

        // each sub-lane writes 2 of the tile's 8 rows
        float* optr = out + ((size_t)h * NSEQ + (size_t)n * CHUNKN + r0 + ii) * EDIM + ei4;
        #pragma unroll
        for (int k = 0; k < 2; k++) {
            int rr = sub * 2 + k;
            ulonglong2 t0; t0.x = c2[rr][0]; t0.y = c2[rr][1];
            ulonglong2 t1; t1.x = c2[rr][2]; t1.y = c2[rr][3];
            *(ulonglong2*)(optr + (size_t)rr * EDIM)      = t0;
            *(ulonglong2*)(optr + (size_t)rr * EDIM + 32) = t1;
        }
    }
}

extern "C" void kernel_launch(void* const* d_in, const int* in_sizes, int n_in,
                              void* d_out, int out_size)
{
    const float* q = (const float*)d_in[0];
    const float* k = (const float*)d_in[1];
    const float* v = (const float*)d_in[2];
    float* out = (float*)d_out;
    float* wts = out + (size_t)NH * NSEQ * EDIM;   // weights follow output in d_out

    size_t smem = (size_t)SMEM_FLOATS * sizeof(float);   // 217088 B
    cudaFuncSetAttribute(chunked_attn_kernel,
                         cudaFuncAttributeMaxDynamicSharedMemorySize, (int)smem);

    dim3 grid(CHUNKN / RT, NCH, NH);   // 8 x 16 x 16 = 2048 blocks
    chunked_attn_kernel<<<grid, 256, smem>>>(q, k, v, out, wts);
}

// round 6
// speedup vs baseline: 1.6512x; 1.6512x over previous
#include <cuda_runtime.h>
#include <math.h>

// Problem constants (B=1)
#define NH     16
#define NSEQ   8192
#define EDIM   64
#define CHUNKN 512
#define NCH    16
#define RT     64      // query rows per block
#define SCALE  0.125f  // 1/sqrt(64)
#define WCOLS  15872   // 512 + 15*1024

// smem leading dims (floats); all vector bases 16B-aligned
#define QT_LD 72
#define KV_LD 260      // 256-col K pass tile (e-major)
#define VS_LD 68       // V row-major 64 + pad
#define S_LD  516

#define SM_QT 0
#define SM_KV (64 * QT_LD)                 // 4608
#define SM_S  (SM_KV + 64 * KV_LD)         // 21248
#define SMEM_FLOATS (SM_S + RT * S_LD)     // 54272 floats = 217088 B

// ---- packed f32x2 helpers ----
#define FMA2(d, a, b)  asm("fma.rn.f32x2 %0, %1, %2, %0;" : "+l"(d) : "l"(a), "l"(b))
#define MUL2(d, a, b)  asm("mul.rn.f32x2 %0, %1, %2;"     : "=l"(d) : "l"(a), "l"(b))
#define ADD2(d, a, b)  asm("add.rn.f32x2 %0, %1, %2;"     : "=l"(d) : "l"(a), "l"(b))
#define PACK2(p, x)    asm("mov.b64 %0, {%1, %1};"        : "=l"(p) : "r"(__float_as_uint(x)))

__global__ __launch_bounds__(512, 1)
void chunked_attn_kernel(const float* __restrict__ query,
                         const float* __restrict__ key,
                         const float* __restrict__ value,
                         float* __restrict__ out,
                         float* __restrict__ wts)
{
    extern __shared__ float sm[];
    float* Qt  = sm + SM_QT;   // Qt[e][i]  (e-major)
    float* KV  = sm + SM_KV;   // K tile KV[e][jj] (e-major) / V tile Vsm[jj][e] (row-major)
    float* S   = sm + SM_S;    // S[i][j]

    const int tid  = threadIdx.x;
    const int lane = tid & 31;
    const int wid  = tid >> 5;           // 0..15

    const int rt = blockIdx.x;           // row tile 0..7
    const int n  = blockIdx.y;           // chunk
    const int h  = blockIdx.z;           // head
    const int r0 = rt * RT;
    const int m  = (n == 0) ? 0 : n - 1; // effective key/value chunk

    const float* qbase = query + ((size_t)h * NSEQ + (size_t)n * CHUNKN + r0) * EDIM;
    const float* kbase = key   + ((size_t)h * NSEQ + (size_t)m * CHUNKN) * EDIM;
    const float* vbase = value + ((size_t)h * NSEQ + (size_t)m * CHUNKN) * EDIM;

    // ---- load Q tile transposed: Qt[e][i] ----
    for (int idx = tid; idx < RT * EDIM; idx += 512) {
        int i = idx >> 6, e = idx & 63;
        Qt[e * QT_LD + i] = qbase[(size_t)i * EDIM + e];
    }

    const int ktmax = rt >> 1;            // highest live 128-key tile
    const int jend  = (ktmax + 1) * 128;
    const int npass = (ktmax + 2) >> 1;   // 256-col GEMM1 passes

    // ==================== GEMM1: S = scale * Q K^T, 64x256 passes ====================
    {
        const int txc = lane;             // 32 col-groups of 8 cols
        const int tyr = wid;              // 16 row-groups of 4 rows
        unsigned long long sp; PACK2(sp, SCALE);

        for (int p = 0; p < npass; p++) {
            const int j0 = p * 256;
            __syncthreads();              // protect KV (also orders Qt on p=0)
            for (int idx = tid; idx < 256 * 64; idx += 512) {
                int jj = idx >> 6, e = idx & 63;
                KV[e * KV_LD + jj] = kbase[(size_t)(j0 + jj) * EDIM + e];
            }
            __syncthreads();

            unsigned long long acc[4][4];
            #pragma unroll
            for (int r = 0; r < 4; r++)
                #pragma unroll
                for (int c = 0; c < 4; c++) acc[r][c] = 0ull;

            const float* qb = Qt + tyr * 4;
            const float* kb = KV + txc * 8;
            #pragma unroll 4
            for (int e = 0; e < EDIM; e++) {
                float4 qv = *(const float4*)(qb + e * QT_LD);        // warp-uniform (broadcast)
                const float* ke = kb + e * KV_LD;
                ulonglong2 k0 = *(const ulonglong2*)ke;              // cols +0..3
                ulonglong2 k1 = *(const ulonglong2*)(ke + 4);        // cols +4..7
                float qs[4] = {qv.x, qv.y, qv.z, qv.w};
                #pragma unroll
                for (int r = 0; r < 4; r++) {
                    unsigned long long qq; PACK2(qq, qs[r]);
                    FMA2(acc[r][0], qq, k0.x);
                    FMA2(acc[r][1], qq, k0.y);
                    FMA2(acc[r][2], qq, k1.x);
                    FMA2(acc[r][3], qq, k1.y);
                }
            }

            #pragma unroll
            for (int r = 0; r < 4; r++) {
                float* srow = S + (tyr * 4 + r) * S_LD + j0 + txc * 8;
                unsigned long long m0, m1, m2, m3;
                MUL2(m0, acc[r][0], sp); MUL2(m1, acc[r][1], sp);
                MUL2(m2, acc[r][2], sp); MUL2(m3, acc[r][3], sp);
                ulonglong2 t0; t0.x = m0; t0.y = m1;
                ulonglong2 t1; t1.x = m2; t1.y = m3;
                *(ulonglong2*)srow       = t0;
                *(ulonglong2*)(srow + 4) = t1;
            }
        }
    }

    __syncthreads();

    // ==================== softmax + weights write (warp per row, 4 rows/warp) ====================
    const int wcolbase = (n == 0) ? 0 : 512 + (n - 1) * 1024;
    for (int i = wid * 4; i < wid * 4 + 4; i++) {
        const int rglob = r0 + i;
        float* srow = S + i * S_LD;

        float mx = -INFINITY;
        for (int j = lane; j <= rglob; j += 32) mx = fmaxf(mx, srow[j]);
        #pragma unroll
        for (int off = 16; off; off >>= 1) mx = fmaxf(mx, __shfl_xor_sync(0xffffffffu, mx, off));

        float sum = 0.f;
        for (int j = lane; j <= rglob; j += 32) {
            float ex = __expf(srow[j] - mx);
            srow[j] = ex;
            sum += ex;
        }
        #pragma unroll
        for (int off = 16; off; off >>= 1) sum += __shfl_xor_sync(0xffffffffu, sum, off);
        float inv = 1.f / sum;

        float* wrow = wts + ((size_t)h * CHUNKN + rglob) * WCOLS + wcolbase;
        for (int j = lane; j < jend; j += 32) {
            float a = (j <= rglob) ? srow[j] * inv : 0.f;
            srow[j] = a;            // zero masked region inside jend for GEMM2
            wrow[j] = a;
        }
        for (int j = jend + lane; j < CHUNKN; j += 32) wrow[j] = 0.f;
        if (n > 0)
            for (int j = CHUNKN + lane; j < 2 * CHUNKN; j += 32) wrow[j] = 0.f;
    }

    // ==================== GEMM2: O = A V, 8rows x 4e tiles, 4-way j-subslice ====================
    {
        const int sub   = tid & 3;            // j sub-slice (interleaved by 4)
        const int tilei = tid >> 2;           // 0..127
        const int ei4   = (tilei & 15) * 4;   // e col base
        const int ii    = (tilei >> 4) * 8;   // row base
        float* Vsm = KV;                      // reuse: Vsm[jj][e], VS_LD

        unsigned long long c2[8][2];
        #pragma unroll
        for (int r = 0; r < 8; r++) { c2[r][0] = 0ull; c2[r][1] = 0ull; }

        for (int kt = 0; kt <= ktmax; kt++) {
            __syncthreads();                  // prior tile consumed / softmax done (kt=0)
            for (int idx = tid; idx < 128 * 16; idx += 512) {
                int jj = idx >> 4, e4 = (idx & 15) << 2;
                *(float4*)(Vsm + jj * VS_LD + e4) =
                    *(const float4*)(vbase + (size_t)(kt * 128 + jj) * EDIM + e4);
            }
            __syncthreads();

            const float* Ab  = S   + ii * S_LD + kt * 128 + sub * 4;
            const float* Vb0 = Vsm + (sub * 4) * VS_LD + ei4;

            #pragma unroll 2
            for (int mm = 0; mm < 8; mm++) {
                float4 ar[8];
                #pragma unroll
                for (int r = 0; r < 8; r++)
                    ar[r] = *(const float4*)(Ab + r * S_LD + mm * 16);   // warp-broadcast
                #pragma unroll
                for (int jr = 0; jr < 4; jr++) {
                    const float* vp = Vb0 + (mm * 16 + jr) * VS_LD;
                    ulonglong2 vv = *(const ulonglong2*)vp;              // e: ei4..ei4+3
                    #pragma unroll
                    for (int r = 0; r < 8; r++) {
                        float av = (jr == 0) ? ar[r].x : (jr == 1) ? ar[r].y
                                 : (jr == 2) ? ar[r].z : ar[r].w;
                        unsigned long long pa; PACK2(pa, av);
                        FMA2(c2[r][0], pa, vv.x);
                        FMA2(c2[r][1], pa, vv.y);
                    }
                }
            }
        }

        // butterfly-reduce the 4 j-subslices (lanes xor 1, xor 2 share a tile)
        #pragma unroll
        for (int r = 0; r < 8; r++)
            #pragma unroll
            for (int c = 0; c < 2; c++) {
                unsigned long long o;
                o = __shfl_xor_sync(0xffffffffu, c2[r][c], 1);
                ADD2(c2[r][c], c2[r][c], o);
                o = __shfl_xor_sync(0xffffffffu, c2[r][c], 2);
                ADD2(c2[r][c], c2[r][c], o);
            }

        // each sub-lane writes 2 of the tile's 8 rows (16B each)
        float* optr = out + ((size_t)h * NSEQ + (size_t)n * CHUNKN + r0 + ii) * EDIM + ei4;
        #pragma unroll
        for (int k = 0; k < 2; k++) {
            int rr = sub * 2 + k;
            ulonglong2 t; t.x = c2[rr][0]; t.y = c2[rr][1];
            *(ulonglong2*)(optr + (size_t)rr * EDIM) = t;
        }
    }
}

extern "C" void kernel_launch(void* const* d_in, const int* in_sizes, int n_in,
                              void* d_out, int out_size)
{
    const float* q = (const float*)d_in[0];
    const float* k = (const float*)d_in[1];
    const float* v = (const float*)d_in[2];
    float* out = (float*)d_out;
    float* wts = out + (size_t)NH * NSEQ * EDIM;   // weights follow output in d_out

    size_t smem = (size_t)SMEM_FLOATS * sizeof(float);   // 217088 B
    cudaFuncSetAttribute(chunked_attn_kernel,
                         cudaFuncAttributeMaxDynamicSharedMemorySize, (int)smem);

    dim3 grid(CHUNKN / RT, NCH, NH);   // 8 x 16 x 16 = 2048 blocks
    chunked_attn_kernel<<<grid, 512, smem>>>(q, k, v, out, wts);
}

// round 8
// speedup vs baseline: 3.4526x; 2.0909x over previous
#include <cuda_runtime.h>
#include <cuda_bf16.h>
#include <cstdint>
#include <math.h>

#define NH     16
#define NSEQ   8192
#define EDIM   64
#define CHUNKN 512
#define NCH    16
#define WCOLS  15872
#define MTILE  128
#define SCALE  0.125f

// ---- SMEM byte offsets (dynamic) ----
// Q/K rows: 144B stride (64 bf16 + 8 pad). Vt rows: 272B stride (128 bf16 + 8 pad).
#define SM_QHI   0
#define SM_QLO   18432
#define SM_KHI   36864
#define SM_KLO   55296
#define SM_VHI   73728
#define SM_VLO   91136
#define SM_SUMS  108544            // 16 warps x 16 rows fp32
#define SM_INV   109568            // 128 fp32
#define SM_TOTAL 110080
#define SM_OBUF  SM_QHI            // alias after GEMM1 done: 128 x 66 fp32 = 33792B

__device__ __forceinline__ uint32_t s2u(const void* p) {
    uint32_t a;
    asm("{ .reg .u64 t; cvta.to.shared.u64 t, %1; cvt.u32.u64 %0, t; }" : "=r"(a) : "l"(p));
    return a;
}
__device__ __forceinline__ void ldmx4(uint32_t addr, uint32_t* r) {
    asm volatile("ldmatrix.sync.aligned.m8n8.x4.shared.b16 {%0,%1,%2,%3}, [%4];"
                 : "=r"(r[0]), "=r"(r[1]), "=r"(r[2]), "=r"(r[3]) : "r"(addr));
}
__device__ __forceinline__ void ldmx2(uint32_t addr, uint32_t* r) {
    asm volatile("ldmatrix.sync.aligned.m8n8.x2.shared.b16 {%0,%1}, [%2];"
                 : "=r"(r[0]), "=r"(r[1]) : "r"(addr));
}
__device__ __forceinline__ void mma16816(float* d, const uint32_t* a, const uint32_t* b) {
    asm volatile("mma.sync.aligned.m16n8k16.row.col.f32.bf16.bf16.f32 "
                 "{%0,%1,%2,%3},{%4,%5,%6,%7},{%8,%9},{%0,%1,%2,%3};"
                 : "+f"(d[0]), "+f"(d[1]), "+f"(d[2]), "+f"(d[3])
                 : "r"(a[0]), "r"(a[1]), "r"(a[2]), "r"(a[3]), "r"(b[0]), "r"(b[1]));
}
// pack two fp32 -> bf16x2: low half = first arg (even col), high = second (odd col)
__device__ __forceinline__ uint32_t packbf(float lo, float hi) {
    uint32_t r;
    asm("cvt.rn.bf16x2.f32 %0, %1, %2;" : "=r"(r) : "f"(hi), "f"(lo));
    return r;
}
__device__ __forceinline__ float bfval(float x) {
    return __bfloat162float(__float2bfloat16(x));
}

__global__ __launch_bounds__(512, 1)
void chunked_attn_mma(const float* __restrict__ query, const float* __restrict__ key,
                      const float* __restrict__ value, float* __restrict__ out,
                      float* __restrict__ wts)
{
    extern __shared__ char smem[];
    const uint32_t sb = s2u(smem);
    const int tid = threadIdx.x, lane = tid & 31, w = tid >> 5;
    const int strip = w & 7;          // 16-row strip within the 128-row tile
    const int kh    = w >> 3;         // 64-col half within a 128-key slab

    const int rt = blockIdx.x;        // 0..3
    const int n  = blockIdx.y, h = blockIdx.z;
    const int r0 = rt * MTILE;
    const int m  = (n == 0) ? 0 : n - 1;
    const int nslab = rt + 1;
    const int jend  = nslab * 128;
    const int wcb   = (n == 0) ? 0 : 512 + (n - 1) * 1024;

    const float* qbase = query + ((size_t)h * NSEQ + (size_t)n * CHUNKN + r0) * EDIM;
    const float* kbase = key   + ((size_t)h * NSEQ + (size_t)m * CHUNKN) * EDIM;
    const float* vbase = value + ((size_t)h * NSEQ + (size_t)m * CHUNKN) * EDIM;

    // ---- zero-fill dead weight columns ----
    {
        const float4 z4 = make_float4(0.f, 0.f, 0.f, 0.f);
        for (int r = w; r < MTILE; r += 16) {
            float* wr = wts + ((size_t)h * CHUNKN + r0 + r) * WCOLS + wcb;
            for (int c = jend + lane * 4; c < 512; c += 128) *(float4*)(wr + c) = z4;
            if (n > 0)
                for (int c = 512 + lane * 4; c < 1024; c += 128) *(float4*)(wr + c) = z4;
        }
    }

    // ---- Q fill: bf16 hi/lo, pre-scaled, row stride 144B ----
    for (int idx = tid; idx < MTILE * 16; idx += 512) {
        int row = idx >> 4, c4 = (idx & 15) << 2;
        float4 qv = *(const float4*)(qbase + (size_t)row * EDIM + c4);
        float f[4] = {qv.x * SCALE, qv.y * SCALE, qv.z * SCALE, qv.w * SCALE};
        uint2 hv, lv;
        hv.x = packbf(f[0], f[1]); hv.y = packbf(f[2], f[3]);
        lv.x = packbf(f[0] - bfval(f[0]), f[1] - bfval(f[1]));
        lv.y = packbf(f[2] - bfval(f[2]), f[3] - bfval(f[3]));
        uint32_t o = (uint32_t)row * 144 + (uint32_t)c4 * 2;
        *(uint2*)(smem + SM_QHI + o) = hv;
        *(uint2*)(smem + SM_QLO + o) = lv;
    }

    float oacc[8][4];
    #pragma unroll
    for (int t = 0; t < 8; t++)
        #pragma unroll
        for (int u = 0; u < 4; u++) oacc[t][u] = 0.f;
    float rs0 = 0.f, rs1 = 0.f;

    const int rlo = r0 + strip * 16 + (lane >> 2);   // chunk-local row (c0/c1)
    const int rhi = rlo + 8;                         // (c2/c3)

    // lane-dependent ldmatrix bases
    const uint32_t aQ = sb + (uint32_t)((strip * 16 + (lane & 15)) * 144 + ((lane >> 4) * 8) * 2);
    const uint32_t bK = sb + SM_KHI +
        (uint32_t)((kh * 64 + (lane & 7)) * 144 + (((lane >> 3) & 1) * 8) * 2);
    const uint32_t bV = sb + SM_VHI +
        (uint32_t)((lane & 7) * 272 + (kh * 64 + ((lane >> 3) & 1) * 8) * 2);

    for (int kt = 0; kt < nslab; kt++) {
        __syncthreads();   // protect K/V buffers from previous slab readers
        // K slab fill (128 x 64, stride 144B)
        for (int idx = tid; idx < 128 * 16; idx += 512) {
            int row = idx >> 4, c4 = (idx & 15) << 2;
            float4 kv = *(const float4*)(kbase + (size_t)(kt * 128 + row) * EDIM + c4);
            float f[4] = {kv.x, kv.y, kv.z, kv.w};
            uint2 hv, lv;
            hv.x = packbf(f[0], f[1]); hv.y = packbf(f[2], f[3]);
            lv.x = packbf(f[0] - bfval(f[0]), f[1] - bfval(f[1]));
            lv.y = packbf(f[2] - bfval(f[2]), f[3] - bfval(f[3]));
            uint32_t o = (uint32_t)row * 144 + (uint32_t)c4 * 2;
            *(uint2*)(smem + SM_KHI + o) = hv;
            *(uint2*)(smem + SM_KLO + o) = lv;
        }
        // Vt slab fill: Vt[e][j], stride 272B
        for (int idx = tid; idx < 128 * 16; idx += 512) {
            int j = idx >> 4, e4 = (idx & 15) << 2;
            float4 vv = *(const float4*)(vbase + (size_t)(kt * 128 + j) * EDIM + e4);
            float f[4] = {vv.x, vv.y, vv.z, vv.w};
            #pragma unroll
            for (int u = 0; u < 4; u++) {
                uint32_t o = (uint32_t)(e4 + u) * 272 + (uint32_t)j * 2;
                *(__nv_bfloat16*)(smem + SM_VHI + o) = __float2bfloat16(f[u]);
                *(__nv_bfloat16*)(smem + SM_VLO + o) = __float2bfloat16(f[u] - bfval(f[u]));
            }
        }
        __syncthreads();

        const bool dead = (kt == rt) && (strip * 16 + 15 < kh * 64);

        float sacc[8][4];
        #pragma unroll
        for (int t = 0; t < 8; t++)
            #pragma unroll
            for (int u = 0; u < 4; u++) sacc[t][u] = 0.f;

        if (!dead) {
            // ---- GEMM1: S strip-half = Q(strip) . K(kh-half)^T, bf16x3 ----
            #pragma unroll
            for (int kc = 0; kc < 4; kc++) {
                uint32_t ah[4], al[4];
                ldmx4(aQ + SM_QHI + kc * 32, ah);
                ldmx4(aQ + SM_QLO + kc * 32, al);
                #pragma unroll
                for (int t = 0; t < 8; t++) {
                    uint32_t bh[2], bl[2];
                    uint32_t ba = bK + (uint32_t)t * 1152 + kc * 32;
                    ldmx2(ba, bh);
                    ldmx2(ba + (SM_KLO - SM_KHI), bl);
                    mma16816(sacc[t], ah, bh);
                    mma16816(sacc[t], ah, bl);
                    mma16816(sacc[t], al, bh);
                }
            }
        }

        // ---- exp + mask + weights STG + pack P (bf16 hi/lo) ----
        uint32_t phi[8][2], plo[8][2];
        {
            float* wlo = wts + ((size_t)h * CHUNKN + rlo) * WCOLS + wcb
                       + kt * 128 + kh * 64 + 2 * (lane & 3);
            float* whi = wlo + (size_t)8 * WCOLS;
            const int cbase = kt * 128 + kh * 64 + 2 * (lane & 3);
            #pragma unroll
            for (int t = 0; t < 8; t++) {
                int c = cbase + t * 8;
                float p00 = (c     <= rlo) ? __expf(sacc[t][0]) : 0.f;
                float p01 = (c + 1 <= rlo) ? __expf(sacc[t][1]) : 0.f;
                float p10 = (c     <= rhi) ? __expf(sacc[t][2]) : 0.f;
                float p11 = (c + 1 <= rhi) ? __expf(sacc[t][3]) : 0.f;
                rs0 += p00 + p01;  rs1 += p10 + p11;
                *(float2*)(wlo + t * 8) = make_float2(p00, p01);
                *(float2*)(whi + t * 8) = make_float2(p10, p11);
                phi[t][0] = packbf(p00, p01);
                phi[t][1] = packbf(p10, p11);
                plo[t][0] = packbf(p00 - bfval(p00), p01 - bfval(p01));
                plo[t][1] = packbf(p10 - bfval(p10), p11 - bfval(p11));
            }
        }

        if (!dead) {
            // ---- GEMM2: O += P(strip, kh-half) . V, A fragments straight from regs ----
            #pragma unroll
            for (int kc = 0; kc < 4; kc++) {
                uint32_t ah[4] = {phi[2*kc][0], phi[2*kc][1], phi[2*kc+1][0], phi[2*kc+1][1]};
                uint32_t al[4] = {plo[2*kc][0], plo[2*kc][1], plo[2*kc+1][0], plo[2*kc+1][1]};
                #pragma unroll
                for (int t2 = 0; t2 < 8; t2++) {
                    uint32_t bh[2], bl[2];
                    uint32_t ba = bV + (uint32_t)t2 * 8 * 272 + kc * 32;
                    ldmx2(ba, bh);
                    ldmx2(ba + (SM_VLO - SM_VHI), bl);
                    mma16816(oacc[t2], ah, bh);
                    mma16816(oacc[t2], ah, bl);
                    mma16816(oacc[t2], al, bh);
                }
            }
        }
    }

    __syncthreads();   // all Q/K/V reads done; OBUF alias + sums now safe

    // ---- rowsum quad-reduce -> sums[w][row] ----
    rs0 += __shfl_xor_sync(0xffffffffu, rs0, 1);
    rs0 += __shfl_xor_sync(0xffffffffu, rs0, 2);
    rs1 += __shfl_xor_sync(0xffffffffu, rs1, 1);
    rs1 += __shfl_xor_sync(0xffffffffu, rs1, 2);
    if ((lane & 3) == 0) {
        float* su = (float*)(smem + SM_SUMS);
        su[w * 16 + (lane >> 2)]     = rs0;
        su[w * 16 + (lane >> 2) + 8] = rs1;
    }
    // kh==0 warps park O partials in smem (stride 66 floats)
    if (kh == 0) {
        float* ob = (float*)(smem + SM_OBUF);
        int row0 = strip * 16 + (lane >> 2);
        #pragma unroll
        for (int t2 = 0; t2 < 8; t2++) {
            int c = t2 * 8 + 2 * (lane & 3);
            *(float2*)(ob + row0 * 66 + c)       = make_float2(oacc[t2][0], oacc[t2][1]);
            *(float2*)(ob + (row0 + 8) * 66 + c) = make_float2(oacc[t2][2], oacc[t2][3]);
        }
    }
    __syncthreads();

    if (tid < 128) {
        const float* su = (const float*)(smem + SM_SUMS);
        int s = tid >> 4, i = tid & 15;
        ((float*)(smem + SM_INV))[tid] = 1.f / (su[s * 16 + i] + su[(s + 8) * 16 + i]);
    }
    __syncthreads();
    const float* invp = (const float*)(smem + SM_INV);

    // ---- O finalize (kh==1 warps): add partner partial, scale, STG ----
    if (kh == 1) {
        const float* ob = (const float*)(smem + SM_OBUF);
        int row0 = strip * 16 + (lane >> 2);
        float iv0 = invp[row0], iv1 = invp[row0 + 8];
        float* op = out + ((size_t)h * NSEQ + (size_t)n * CHUNKN + r0 + row0) * EDIM;
        #pragma unroll
        for (int t2 = 0; t2 < 8; t2++) {
            int c = t2 * 8 + 2 * (lane & 3);
            float2 p0 = *(const float2*)(ob + row0 * 66 + c);
            float2 p1 = *(const float2*)(ob + (row0 + 8) * 66 + c);
            *(float2*)(op + c) =
                make_float2((oacc[t2][0] + p0.x) * iv0, (oacc[t2][1] + p0.y) * iv0);
            *(float2*)(op + (size_t)8 * EDIM + c) =
                make_float2((oacc[t2][2] + p1.x) * iv1, (oacc[t2][3] + p1.y) * iv1);
        }
    }

    // ---- rescale weights in-place (live region only) ----
    for (int r = w; r < MTILE; r += 16) {
        float iv = invp[r];
        float* wr = wts + ((size_t)h * CHUNKN + r0 + r) * WCOLS + wcb;
        for (int c = lane * 4; c < jend; c += 128) {
            float4 t = *(float4*)(wr + c);
            t.x *= iv; t.y *= iv; t.z *= iv; t.w *= iv;
            *(float4*)(wr + c) = t;
        }
    }
}

extern "C" void kernel_launch(void* const* d_in, const int* in_sizes, int n_in,
                              void* d_out, int out_size)
{
    const float* q = (const float*)d_in[0];
    const float* k = (const float*)d_in[1];
    const float* v = (const float*)d_in[2];
    float* out = (float*)d_out;
    float* wts = out + (size_t)NH * NSEQ * EDIM;

    cudaFuncSetAttribute(chunked_attn_mma,
                         cudaFuncAttributeMaxDynamicSharedMemorySize, SM_TOTAL);
    dim3 grid(CHUNKN / MTILE, NCH, NH);   // 4 x 16 x 16 = 1024 CTAs
    chunked_attn_mma<<<grid, 512, SM_TOTAL>>>(q, k, v, out, wts);
}

// round 9
// speedup vs baseline: 4.4575x; 1.2911x over previous
#include <cuda_runtime.h>
#include <cuda_bf16.h>
#include <cstdint>
#include <math.h>

#define NH     16
#define NSEQ   8192
#define EDIM   64
#define CHUNKN 512
#define NCH    16
#define WCOLS  15872
#define MTILE  128
#define SCALE  0.125f

// ---- bf16 hi/lo scratch planes: [0]=Khi [1]=Klo [2]=Vhi [3]=Vlo ----
#define SCR_ELEMS (16u * 8192u * 64u)   // 8388608
__device__ __nv_bfloat16 g_scr[4][SCR_ELEMS];

// ---- SMEM byte offsets; all K/V/Q rows stride 144B (64 bf16 + 8 pad) ----
#define SM_QHI   0
#define SM_QLO   18432
#define SM_K0    36864          // hi at +0, lo at +18432
#define SM_K1    73728
#define SM_V0    110592
#define SM_V1    147456
#define SM_SUMS  184320         // 16 warps x 16 rows fp32
#define SM_INV   185344         // 128 fp32
#define SM_TOTAL 185856
#define SM_OBUF  SM_QHI         // alias after Q frags preloaded: 128 x 66 fp32

__device__ __forceinline__ uint32_t s2u(const void* p) {
    uint32_t a;
    asm("{ .reg .u64 t; cvta.to.shared.u64 t, %1; cvt.u32.u64 %0, t; }" : "=r"(a) : "l"(p));
    return a;
}
__device__ __forceinline__ void ldmx4(uint32_t addr, uint32_t* r) {
    asm volatile("ldmatrix.sync.aligned.m8n8.x4.shared.b16 {%0,%1,%2,%3}, [%4];"
                 : "=r"(r[0]), "=r"(r[1]), "=r"(r[2]), "=r"(r[3]) : "r"(addr));
}
__device__ __forceinline__ void ldmx2(uint32_t addr, uint32_t* r) {
    asm volatile("ldmatrix.sync.aligned.m8n8.x2.shared.b16 {%0,%1}, [%2];"
                 : "=r"(r[0]), "=r"(r[1]) : "r"(addr));
}
__device__ __forceinline__ void ldmx2t(uint32_t addr, uint32_t* r) {
    asm volatile("ldmatrix.sync.aligned.m8n8.x2.trans.shared.b16 {%0,%1}, [%2];"
                 : "=r"(r[0]), "=r"(r[1]) : "r"(addr));
}
__device__ __forceinline__ void mma16816(float* d, const uint32_t* a, const uint32_t* b) {
    asm volatile("mma.sync.aligned.m16n8k16.row.col.f32.bf16.bf16.f32 "
                 "{%0,%1,%2,%3},{%4,%5,%6,%7},{%8,%9},{%0,%1,%2,%3};"
                 : "+f"(d[0]), "+f"(d[1]), "+f"(d[2]), "+f"(d[3])
                 : "r"(a[0]), "r"(a[1]), "r"(a[2]), "r"(a[3]), "r"(b[0]), "r"(b[1]));
}
__device__ __forceinline__ uint32_t packbf(float lo, float hi) {
    uint32_t r;
    asm("cvt.rn.bf16x2.f32 %0, %1, %2;" : "=r"(r) : "f"(hi), "f"(lo));
    return r;
}
__device__ __forceinline__ float bfval(float x) {
    return __bfloat162float(__float2bfloat16(x));
}
__device__ __forceinline__ void cpa16(uint32_t dst, const void* src) {
    asm volatile("cp.async.cg.shared.global [%0], [%1], 16;" :: "r"(dst), "l"(src));
}
#define CP_COMMIT() asm volatile("cp.async.commit_group;" ::: "memory")
#define CP_WAIT(n)  asm volatile("cp.async.wait_group %0;" :: "n"(n) : "memory")

// =================== pre-kernel: fp32 -> bf16 hi/lo planes ===================
__global__ __launch_bounds__(512)
void convert_kv(const float* __restrict__ key, const float* __restrict__ value)
{
    uint32_t i = blockIdx.x * 512u + threadIdx.x;      // float4 index, exact grid
    float4 kv = ((const float4*)key)[i];
    float4 vv = ((const float4*)value)[i];
    uint2 khi, klo, vhi, vlo;
    khi.x = packbf(kv.x, kv.y); khi.y = packbf(kv.z, kv.w);
    klo.x = packbf(kv.x - bfval(kv.x), kv.y - bfval(kv.y));
    klo.y = packbf(kv.z - bfval(kv.z), kv.w - bfval(kv.w));
    vhi.x = packbf(vv.x, vv.y); vhi.y = packbf(vv.z, vv.w);
    vlo.x = packbf(vv.x - bfval(vv.x), vv.y - bfval(vv.y));
    vlo.y = packbf(vv.z - bfval(vv.z), vv.w - bfval(vv.w));
    ((uint2*)g_scr[0])[i] = khi;
    ((uint2*)g_scr[1])[i] = klo;
    ((uint2*)g_scr[2])[i] = vhi;
    ((uint2*)g_scr[3])[i] = vlo;
}

// =================== main kernel ===================
__global__ __launch_bounds__(512, 1)
void chunked_attn_mma(const float* __restrict__ query, float* __restrict__ out,
                      float* __restrict__ wts)
{
    extern __shared__ char smem[];
    const uint32_t sb = s2u(smem);
    const int tid = threadIdx.x, lane = tid & 31, w = tid >> 5;
    const int strip = w & 7;          // 16-row strip
    const int kh    = w >> 3;         // 64-col half of the 128-key slab

    const int rt = 3 - blockIdx.x;    // long CTAs first
    const int n  = blockIdx.y, h = blockIdx.z;
    const int r0 = rt * MTILE;
    const int m  = (n == 0) ? 0 : n - 1;
    const int nslab = rt + 1;
    const int jend  = nslab * 128;
    const int wcb   = (n == 0) ? 0 : 512 + (n - 1) * 1024;

    const float* qbase = query + ((size_t)h * NSEQ + (size_t)n * CHUNKN + r0) * EDIM;
    const uint32_t gjbase = (uint32_t)h * NSEQ + (uint32_t)m * CHUNKN;   // key-row base

    const uint32_t kbuf[2] = {sb + SM_K0, sb + SM_K1};
    const uint32_t vbuf[2] = {sb + SM_V0, sb + SM_V1};

    // ---- prefetch slab 0 (cp.async), then do local fills while it flies ----
    {
        for (int i = tid; i < 4096; i += 512) {
            int arr = i >> 10, row = (i >> 3) & 127, seg = i & 7;
            uint32_t base = (arr < 2) ? kbuf[0] : vbuf[0];
            uint32_t dst = base + ((arr & 1) ? 18432u : 0u) + (uint32_t)row * 144 + seg * 16;
            const __nv_bfloat16* src = g_scr[arr] + ((size_t)(gjbase + row) << 6) + seg * 8;
            cpa16(dst, src);
        }
        CP_COMMIT();
    }

    // ---- zero-fill dead weight columns ----
    {
        const float4 z4 = make_float4(0.f, 0.f, 0.f, 0.f);
        for (int r = w; r < MTILE; r += 16) {
            float* wr = wts + ((size_t)h * CHUNKN + r0 + r) * WCOLS + wcb;
            for (int c = jend + lane * 4; c < 512; c += 128) *(float4*)(wr + c) = z4;
            if (n > 0)
                for (int c = 512 + lane * 4; c < 1024; c += 128) *(float4*)(wr + c) = z4;
        }
    }

    // ---- Q fill: bf16 hi/lo, pre-scaled ----
    for (int idx = tid; idx < MTILE * 16; idx += 512) {
        int row = idx >> 4, c4 = (idx & 15) << 2;
        float4 qv = *(const float4*)(qbase + (size_t)row * EDIM + c4);
        float f[4] = {qv.x * SCALE, qv.y * SCALE, qv.z * SCALE, qv.w * SCALE};
        uint2 hv, lv;
        hv.x = packbf(f[0], f[1]); hv.y = packbf(f[2], f[3]);
        lv.x = packbf(f[0] - bfval(f[0]), f[1] - bfval(f[1]));
        lv.y = packbf(f[2] - bfval(f[2]), f[3] - bfval(f[3]));
        uint32_t o = (uint32_t)row * 144 + (uint32_t)c4 * 2;
        *(uint2*)(smem + SM_QHI + o) = hv;
        *(uint2*)(smem + SM_QLO + o) = lv;
    }
    __syncthreads();   // Q visible

    // ---- preload Q fragments (fixed for all slabs) ----
    uint32_t qh[4][4], ql[4][4];
    {
        const uint32_t aQ = sb + (uint32_t)((strip * 16 + (lane & 15)) * 144 + (lane >> 4) * 16);
        #pragma unroll
        for (int kc = 0; kc < 4; kc++) {
            ldmx4(aQ + SM_QHI + kc * 32, qh[kc]);
            ldmx4(aQ + SM_QLO + kc * 32, ql[kc]);
        }
    }

    float oacc[8][4];
    #pragma unroll
    for (int t = 0; t < 8; t++)
        #pragma unroll
        for (int u = 0; u < 4; u++) oacc[t][u] = 0.f;
    float rs0 = 0.f, rs1 = 0.f;

    const int rlo = r0 + strip * 16 + (lane >> 2);
    const int rhi = rlo + 8;
    const uint32_t bKoff = (uint32_t)((kh * 64 + (lane & 7)) * 144 + ((lane >> 3) & 1) * 16);
    const uint32_t bVoff = (uint32_t)((kh * 64 + (lane & 15)) * 144);

    for (int kt = 0; kt < nslab; kt++) {
        const int p = kt & 1;
        if (kt + 1 < nslab) {   // prefetch next slab into the other buffer
            for (int i = tid; i < 4096; i += 512) {
                int arr = i >> 10, row = (i >> 3) & 127, seg = i & 7;
                uint32_t base = (arr < 2) ? kbuf[1 - p] : vbuf[1 - p];
                uint32_t dst = base + ((arr & 1) ? 18432u : 0u) + (uint32_t)row * 144 + seg * 16;
                const __nv_bfloat16* src =
                    g_scr[arr] + ((size_t)(gjbase + (kt + 1) * 128 + row) << 6) + seg * 8;
                cpa16(dst, src);
            }
            CP_COMMIT();
            CP_WAIT(1);
        } else {
            CP_WAIT(0);
        }
        __syncthreads();        // slab p complete for all warps

        const bool dead = (kt == rt) && (strip * 16 + 15 < kh * 64);
        const uint32_t bK = kbuf[p] + bKoff;
        const uint32_t bV = vbuf[p] + bVoff;

        float sacc[8][4];
        #pragma unroll
        for (int t = 0; t < 8; t++)
            #pragma unroll
            for (int u = 0; u < 4; u++) sacc[t][u] = 0.f;

        if (!dead) {
            #pragma unroll
            for (int kc = 0; kc < 4; kc++) {
                #pragma unroll
                for (int t = 0; t < 8; t++) {
                    uint32_t bh[2], bl[2];
                    uint32_t ba = bK + (uint32_t)t * 1152 + kc * 32;
                    ldmx2(ba, bh);
                    ldmx2(ba + 18432, bl);
                    mma16816(sacc[t], qh[kc], bh);
                    mma16816(sacc[t], qh[kc], bl);
                    mma16816(sacc[t], ql[kc], bh);
                }
            }
        }

        // ---- exp + mask + weights STG + pack P ----
        uint32_t phi[8][2], plo[8][2];
        {
            float* wlo = wts + ((size_t)h * CHUNKN + rlo) * WCOLS + wcb
                       + kt * 128 + kh * 64 + 2 * (lane & 3);
            float* whi = wlo + (size_t)8 * WCOLS;
            const int cbase = kt * 128 + kh * 64 + 2 * (lane & 3);
            #pragma unroll
            for (int t = 0; t < 8; t++) {
                int c = cbase + t * 8;
                float p00 = (c     <= rlo) ? __expf(sacc[t][0]) : 0.f;
                float p01 = (c + 1 <= rlo) ? __expf(sacc[t][1]) : 0.f;
                float p10 = (c     <= rhi) ? __expf(sacc[t][2]) : 0.f;
                float p11 = (c + 1 <= rhi) ? __expf(sacc[t][3]) : 0.f;
                rs0 += p00 + p01;  rs1 += p10 + p11;
                *(float2*)(wlo + t * 8) = make_float2(p00, p01);
                *(float2*)(whi + t * 8) = make_float2(p10, p11);
                phi[t][0] = packbf(p00, p01);
                phi[t][1] = packbf(p10, p11);
                plo[t][0] = packbf(p00 - bfval(p00), p01 - bfval(p01));
                plo[t][1] = packbf(p10 - bfval(p10), p11 - bfval(p11));
            }
        }

        if (!dead) {
            // ---- GEMM2: O += P . V ; V via ldmatrix.trans from row-major V[j][e] ----
            #pragma unroll
            for (int kc = 0; kc < 4; kc++) {
                uint32_t ah[4] = {phi[2*kc][0], phi[2*kc][1], phi[2*kc+1][0], phi[2*kc+1][1]};
                uint32_t al[4] = {plo[2*kc][0], plo[2*kc][1], plo[2*kc+1][0], plo[2*kc+1][1]};
                #pragma unroll
                for (int t2 = 0; t2 < 8; t2++) {
                    uint32_t bh[2], bl[2];
                    uint32_t ba = bV + (uint32_t)kc * 2304 + t2 * 16;
                    ldmx2t(ba, bh);
                    ldmx2t(ba + 18432, bl);
                    mma16816(oacc[t2], ah, bh);
                    mma16816(oacc[t2], ah, bl);
                    mma16816(oacc[t2], al, bh);
                }
            }
        }
        __syncthreads();   // all reads of buf p done before it is refilled
    }

    // ---- rowsum quad-reduce ----
    rs0 += __shfl_xor_sync(0xffffffffu, rs0, 1);
    rs0 += __shfl_xor_sync(0xffffffffu, rs0, 2);
    rs1 += __shfl_xor_sync(0xffffffffu, rs1, 1);
    rs1 += __shfl_xor_sync(0xffffffffu, rs1, 2);
    if ((lane & 3) == 0) {
        float* su = (float*)(smem + SM_SUMS);
        su[w * 16 + (lane >> 2)]     = rs0;
        su[w * 16 + (lane >> 2) + 8] = rs1;
    }
    if (kh == 0) {   // park O partials (stride 66 floats)
        float* ob = (float*)(smem + SM_OBUF);
        int row0 = strip * 16 + (lane >> 2);
        #pragma unroll
        for (int t2 = 0; t2 < 8; t2++) {
            int c = t2 * 8 + 2 * (lane & 3);
            *(float2*)(ob + row0 * 66 + c)       = make_float2(oacc[t2][0], oacc[t2][1]);
            *(float2*)(ob + (row0 + 8) * 66 + c) = make_float2(oacc[t2][2], oacc[t2][3]);
        }
    }
    __syncthreads();

    if (tid < 128) {
        const float* su = (const float*)(smem + SM_SUMS);
        int s = tid >> 4, i = tid & 15;
        ((float*)(smem + SM_INV))[tid] = 1.f / (su[s * 16 + i] + su[(s + 8) * 16 + i]);
    }
    __syncthreads();
    const float* invp = (const float*)(smem + SM_INV);

    if (kh == 1) {
        const float* ob = (const float*)(smem + SM_OBUF);
        int row0 = strip * 16 + (lane >> 2);
        float iv0 = invp[row0], iv1 = invp[row0 + 8];
        float* op = out + ((size_t)h * NSEQ + (size_t)n * CHUNKN + r0 + row0) * EDIM;
        #pragma unroll
        for (int t2 = 0; t2 < 8; t2++) {
            int c = t2 * 8 + 2 * (lane & 3);
            float2 p0 = *(const float2*)(ob + row0 * 66 + c);
            float2 p1 = *(const float2*)(ob + (row0 + 8) * 66 + c);
            *(float2*)(op + c) =
                make_float2((oacc[t2][0] + p0.x) * iv0, (oacc[t2][1] + p0.y) * iv0);
            *(float2*)(op + (size_t)8 * EDIM + c) =
                make_float2((oacc[t2][2] + p1.x) * iv1, (oacc[t2][3] + p1.y) * iv1);
        }
    }

    // ---- rescale weights in-place (live region, L2-warm) ----
    for (int r = w; r < MTILE; r += 16) {
        float iv = invp[r];
        float* wr = wts + ((size_t)h * CHUNKN + r0 + r) * WCOLS + wcb;
        for (int c = lane * 4; c < jend; c += 128) {
            float4 t = *(float4*)(wr + c);
            t.x *= iv; t.y *= iv; t.z *= iv; t.w *= iv;
            *(float4*)(wr + c) = t;
        }
    }
}

extern "C" void kernel_launch(void* const* d_in, const int* in_sizes, int n_in,
                              void* d_out, int out_size)
{
    const float* q = (const float*)d_in[0];
    const float* k = (const float*)d_in[1];
    const float* v = (const float*)d_in[2];
    float* out = (float*)d_out;
    float* wts = out + (size_t)NH * NSEQ * EDIM;

    convert_kv<<<SCR_ELEMS / 4 / 512, 512>>>(k, v);   // 4096 blocks

    cudaFuncSetAttribute(chunked_attn_mma,
                         cudaFuncAttributeMaxDynamicSharedMemorySize, SM_TOTAL);
    dim3 grid(CHUNKN / MTILE, NCH, NH);   // 4 x 16 x 16 = 1024 CTAs
    chunked_attn_mma<<<grid, 512, SM_TOTAL>>>(q, out, wts);
}